// round 1
// baseline (speedup 1.0000x reference)
#include <cuda_runtime.h>
#include <math.h>

// Problem constants
#define BDIM   2
#define VDIM   162
#define SDIM   4096
#define VS     (VDIM * SDIM)        // 663552
#define ODIM   32
#define KCH    5
#define F1     16
#define F2     32
#define MAXELEM ((size_t)BDIM * ODIM * VS)   // 42,467,328 floats (169.9 MB)

// Scratch (static device globals: allowed; no runtime allocation)
__device__ float g_t1[BDIM * ODIM * VS];
__device__ float g_t2[BDIM * ODIM * VS];
__device__ float g_t3[BDIM * ODIM * VS];
__device__ float g_t4[BDIM * ODIM * VS];
__device__ float g_y [BDIM * ODIM * VS];
__device__ float g_h [BDIM * ODIM * VS];
__device__ float g_sum[ODIM];
__device__ float g_sumsq[ODIM];
__device__ float g_scale[ODIM];
__device__ float g_shift[ODIM];

// Buffer selectors: 0..3 = g_t1..g_t4, 4 = g_h, 5 = external param, -1 = none
__device__ __forceinline__ const float* sel_cbuf(int sel, const float* ext) {
    switch (sel) {
        case 0: return g_t1; case 1: return g_t2; case 2: return g_t3;
        case 3: return g_t4; case 4: return g_h;  case 5: return ext;
        default: return nullptr;
    }
}
__device__ __forceinline__ float* sel_mbuf(int sel, float* ext) {
    switch (sel) {
        case 0: return g_t1; case 1: return g_t2; case 2: return g_t3;
        case 3: return g_t4; case 4: return g_h;  case 5: return ext;
        default: return nullptr;
    }
}

// ---------------------------------------------------------------------------
// cheb_step: per (b,f) slice GEMM over the V dimension.
//   dst[v_out, s] = alpha * sum_v lap[v_out, v] * src[v, s]  ( - prev[v_out,s] if prev)
// lap is exactly symmetric, so we read lap rows (coalesced) as B[k][n].
// GEMM view: M = s (4096), N = v_out (162, tiled by 64), K = v (162 = 3*54).
// Block 128 threads, tile 128x64, per-thread 8x8 (4+4 split).
// ---------------------------------------------------------------------------
__global__ __launch_bounds__(128) void cheb_step(
    const float* __restrict__ ext, int srcSel, int prevSel, int dstSel,
    const float* __restrict__ lap, float alpha)
{
    __shared__ float As[54][128];
    __shared__ float Bs[54][64];

    const int tid = threadIdx.x;
    const int tx  = tid & 15;    // m direction (16)
    const int ty  = tid >> 4;    // n direction (8)
    const size_t slice = blockIdx.z;
    const int m0 = blockIdx.x * 128;
    const int n0 = blockIdx.y * 64;

    const float* src  = sel_cbuf(srcSel,  ext);
    const float* prev = sel_cbuf(prevSel, ext);
    float*       dst  = sel_mbuf(dstSel,  nullptr);

    const float* srcS = src + slice * (size_t)VS;

    float acc[8][8];
#pragma unroll
    for (int i = 0; i < 8; i++)
#pragma unroll
        for (int j = 0; j < 8; j++) acc[i][j] = 0.f;

    for (int k0 = 0; k0 < VDIM; k0 += 54) {
        // A tile: As[k][m] = src[(k0+k), m0+m]   (54 x 128, vectorized)
        for (int i = tid; i < 54 * 32; i += 128) {
            int k = i >> 5, mq = i & 31;
            *(float4*)&As[k][mq * 4] =
                *(const float4*)&srcS[(size_t)(k0 + k) * SDIM + m0 + mq * 4];
        }
        // B tile: Bs[k][n] = lap[(k0+k)*V + (n0+n)], zero-pad n beyond V
        for (int i = tid; i < 54 * 64; i += 128) {
            int k = i >> 6, n = i & 63;
            float v = 0.f;
            if (n0 + n < VDIM) v = lap[(k0 + k) * VDIM + n0 + n];
            Bs[k][n] = v;
        }
        __syncthreads();

#pragma unroll 2
        for (int k = 0; k < 54; k++) {
            float a[8], b[8];
            *(float4*)&a[0] = *(float4*)&As[k][tx * 4];
            *(float4*)&a[4] = *(float4*)&As[k][tx * 4 + 64];
            *(float4*)&b[0] = *(float4*)&Bs[k][ty * 4];
            *(float4*)&b[4] = *(float4*)&Bs[k][ty * 4 + 32];
#pragma unroll
            for (int i = 0; i < 8; i++)
#pragma unroll
                for (int j = 0; j < 8; j++)
                    acc[i][j] += b[i] * a[j];
        }
        __syncthreads();
    }

    const float* prevS = prev ? prev + slice * (size_t)VS : nullptr;
    float*       dstS  = dst + slice * (size_t)VS;

#pragma unroll
    for (int i = 0; i < 8; i++) {
        int n = n0 + ((i < 4) ? (ty * 4 + i) : (32 + ty * 4 + i - 4));
        if (n >= VDIM) continue;
        size_t rb = (size_t)n * SDIM + m0;
        float4 v0, v1;
        v0.x = alpha * acc[i][0]; v0.y = alpha * acc[i][1];
        v0.z = alpha * acc[i][2]; v0.w = alpha * acc[i][3];
        v1.x = alpha * acc[i][4]; v1.y = alpha * acc[i][5];
        v1.z = alpha * acc[i][6]; v1.w = alpha * acc[i][7];
        if (prevS) {
            float4 p0 = *(const float4*)&prevS[rb + tx * 4];
            float4 p1 = *(const float4*)&prevS[rb + 64 + tx * 4];
            v0.x -= p0.x; v0.y -= p0.y; v0.z -= p0.z; v0.w -= p0.w;
            v1.x -= p1.x; v1.y -= p1.y; v1.z -= p1.z; v1.w -= p1.w;
        }
        *(float4*)&dstS[rb + tx * 4]      = v0;
        *(float4*)&dstS[rb + 64 + tx * 4] = v1;
    }
}

// ---------------------------------------------------------------------------
// combine: y[b,o,v,s] = bias[o] + sum_{k,f} w[k,f,o] * t_k[b,f,v,s]
// GEMM: C[o(32), n(256 tile)] with K = KF (80 / 160).
// Fused BN statistics (sum, sumsq per channel) via smem + global atomics.
// Block 128 threads, per-thread 8(o) x 8(n).
// ---------------------------------------------------------------------------
__global__ __launch_bounds__(128) void combine(
    const float* __restrict__ x0ext, int x0Sel, int Fin,
    const float* __restrict__ w, const float* __restrict__ bias)
{
    const int KF = KCH * Fin;           // 80 or 160
    __shared__ float Ws[KCH * F2][32];  // up to 160 x 32
    __shared__ float Ts[16][256];
    __shared__ const float* rows[KCH * F2];
    __shared__ float s_sum[ODIM], s_sq[ODIM];

    const int tid = threadIdx.x;
    const int b   = blockIdx.y;
    const size_t n0 = (size_t)blockIdx.x * 256;

    const float* x0 = sel_cbuf(x0Sel, x0ext);
    const float* bufs[KCH] = {x0, g_t1, g_t2, g_t3, g_t4};

    for (int i = tid; i < KF; i += 128) {
        int k = i / Fin, f = i % Fin;
        rows[i] = bufs[k] + ((size_t)(b * Fin + f)) * VS;
    }
    for (int i = tid; i < KF * 32; i += 128) Ws[0][i] = w[i];
    if (tid < ODIM) { s_sum[tid] = 0.f; s_sq[tid] = 0.f; }
    __syncthreads();

    const int to = tid & 3;   // o direction (4)
    const int tn = tid >> 2;  // n direction (32)

    float acc[8][8];
#pragma unroll
    for (int i = 0; i < 8; i++)
#pragma unroll
        for (int j = 0; j < 8; j++) acc[i][j] = 0.f;

    for (int kc0 = 0; kc0 < KF; kc0 += 16) {
        for (int i = tid; i < 16 * 64; i += 128) {
            int kk = i >> 6, jq = i & 63;
            *(float4*)&Ts[kk][jq * 4] =
                *(const float4*)&rows[kc0 + kk][n0 + jq * 4];
        }
        __syncthreads();
#pragma unroll 2
        for (int kk = 0; kk < 16; kk++) {
            float a[8], bb[8];
            *(float4*)&a[0]  = *(float4*)&Ws[kc0 + kk][to * 4];
            *(float4*)&a[4]  = *(float4*)&Ws[kc0 + kk][16 + to * 4];
            *(float4*)&bb[0] = *(float4*)&Ts[kk][tn * 4];
            *(float4*)&bb[4] = *(float4*)&Ts[kk][128 + tn * 4];
#pragma unroll
            for (int i = 0; i < 8; i++)
#pragma unroll
                for (int j = 0; j < 8; j++)
                    acc[i][j] += a[i] * bb[j];
        }
        __syncthreads();
    }

#pragma unroll
    for (int i = 0; i < 8; i++) {
        int o = (i < 4) ? (to * 4 + i) : (16 + to * 4 + i - 4);
        float bo = bias[o];
        float* yo = g_y + ((size_t)(b * ODIM + o)) * VS + n0;
        float4 v0, v1;
        v0.x = acc[i][0] + bo; v0.y = acc[i][1] + bo;
        v0.z = acc[i][2] + bo; v0.w = acc[i][3] + bo;
        v1.x = acc[i][4] + bo; v1.y = acc[i][5] + bo;
        v1.z = acc[i][6] + bo; v1.w = acc[i][7] + bo;
        *(float4*)&yo[tn * 4]       = v0;
        *(float4*)&yo[128 + tn * 4] = v1;
        float ps = v0.x + v0.y + v0.z + v0.w + v1.x + v1.y + v1.z + v1.w;
        float pq = v0.x*v0.x + v0.y*v0.y + v0.z*v0.z + v0.w*v0.w
                 + v1.x*v1.x + v1.y*v1.y + v1.z*v1.z + v1.w*v1.w;
        atomicAdd(&s_sum[o], ps);
        atomicAdd(&s_sq[o],  pq);
    }
    __syncthreads();
    if (tid < ODIM) {
        atomicAdd(&g_sum[tid],   s_sum[tid]);
        atomicAdd(&g_sumsq[tid], s_sq[tid]);
    }
}

__global__ void zero_stats() {
    int i = threadIdx.x;
    if (i < ODIM) { g_sum[i] = 0.f; g_sumsq[i] = 0.f; }
}

__global__ void finalize_stats(const float* __restrict__ gamma,
                               const float* __restrict__ beta, float ncnt)
{
    int o = threadIdx.x;
    if (o < ODIM) {
        float mean = g_sum[o] / ncnt;
        float var  = g_sumsq[o] / ncnt - mean * mean;
        float sc   = gamma[o] * rsqrtf(var + 1e-5f);
        g_scale[o] = sc;
        g_shift[o] = beta[o] - mean * sc;
    }
}

// norm_relu: out = relu(y * scale[o] + shift[o]); writes g_h or external d_out
__global__ void norm_relu(float* __restrict__ extOut, int useExt)
{
    float* out = useExt ? extOut : g_h;
    const size_t total4 = MAXELEM / 4;
    const size_t stride = (size_t)gridDim.x * blockDim.x;
    for (size_t i = (size_t)blockIdx.x * blockDim.x + threadIdx.x;
         i < total4; i += stride) {
        size_t e = i * 4;
        int o = (int)((e / VS) % ODIM);
        float sc = g_scale[o], sh = g_shift[o];
        float4 v = ((const float4*)g_y)[i];
        v.x = fmaxf(fmaf(v.x, sc, sh), 0.f);
        v.y = fmaxf(fmaf(v.y, sc, sh), 0.f);
        v.z = fmaxf(fmaf(v.z, sc, sh), 0.f);
        v.w = fmaxf(fmaf(v.w, sc, sh), 0.f);
        ((float4*)out)[i] = v;
    }
}

// ---------------------------------------------------------------------------
extern "C" void kernel_launch(void* const* d_in, const int* in_sizes, int n_in,
                              void* d_out, int out_size)
{
    const float* x   = (const float*)d_in[0];
    const float* lap = (const float*)d_in[1];
    const float* w1  = (const float*)d_in[2];
    const float* b1  = (const float*)d_in[3];
    const float* g1  = (const float*)d_in[4];
    const float* be1 = (const float*)d_in[5];
    const float* w2  = (const float*)d_in[6];
    const float* b2  = (const float*)d_in[7];
    const float* g2  = (const float*)d_in[8];
    const float* be2 = (const float*)d_in[9];
    float* out = (float*)d_out;
    (void)in_sizes; (void)n_in; (void)out_size;

    const float ncnt = (float)((size_t)BDIM * VS);
    dim3 gc1(SDIM / 128, 3, BDIM * F1);   // 32 x 3 x 32
    dim3 gc2(SDIM / 128, 3, BDIM * F2);   // 32 x 3 x 64
    dim3 gcomb(VS / 256, BDIM);           // 2592 x 2

    // ---- Layer 1 (Fin = 16, t0 = x) ----
    cheb_step<<<gc1, 128>>>(x, 5, -1, 0, lap, 1.f);   // t1 = L x
    cheb_step<<<gc1, 128>>>(x, 0,  5, 1, lap, 2.f);   // t2 = 2 L t1 - x
    cheb_step<<<gc1, 128>>>(x, 1,  0, 2, lap, 2.f);   // t3 = 2 L t2 - t1
    cheb_step<<<gc1, 128>>>(x, 2,  1, 3, lap, 2.f);   // t4 = 2 L t3 - t2
    zero_stats<<<1, 32>>>();
    combine<<<gcomb, 128>>>(x, 5, F1, w1, b1);        // y = bias + sum wk*tk (+stats)
    finalize_stats<<<1, 32>>>(g1, be1, ncnt);
    norm_relu<<<2048, 256>>>(nullptr, 0);             // h = relu(bn(y))

    // ---- Layer 2 (Fin = 32, t0 = h) ----
    cheb_step<<<gc2, 128>>>(nullptr, 4, -1, 0, lap, 1.f);
    cheb_step<<<gc2, 128>>>(nullptr, 0,  4, 1, lap, 2.f);
    cheb_step<<<gc2, 128>>>(nullptr, 1,  0, 2, lap, 2.f);
    cheb_step<<<gc2, 128>>>(nullptr, 2,  1, 3, lap, 2.f);
    zero_stats<<<1, 32>>>();
    combine<<<gcomb, 128>>>(nullptr, 4, F2, w2, b2);
    finalize_stats<<<1, 32>>>(g2, be2, ncnt);
    norm_relu<<<2048, 256>>>(out, 1);                 // d_out = relu(bn(y))
}